// round 13
// baseline (speedup 1.0000x reference)
#include <cuda_runtime.h>

// Inputs (metadata order):
// 0: user_id  int32 [16384]
// 1: item_id  int32 [16384]
// 2: category int32 [16384]
// 3: emb_user f32 [100000]
// 4: emb_item f32 [50000]
// 5: emb_cat  f32 [1000]
// 6: cross_w  f32 [150000000]
// out: f32 [16384]
//
// out[i] = emb_user[u] + emb_item[it] + emb_cat[c]
//        + cross_w[u*1000 + c] + cross_w[1e8 + it*1000 + c]
//
// FINAL converged design (evidence R1-R12):
//  - Latency-bound micro-kernel at the graph-replay floor (~5.8us fixed;
//    body ~0.5-0.7us = index load -> 5 independent gathers, 2 DRAM hops).
//  - Run-to-run variance is +/-0.3us (R7 vs R12, identical binary:
//    6.34 vs 6.66). All geometry deltas tested fall inside that band or
//    regress: 4x vectorization -0.3us worse, 64x256 -0.3us worse.
//  - Measured optimum: 1 elem/thread, 128 CTAs x 128 threads (one CTA/SM,
//    one warp per SMSP), minimal body, no bounds check (exact cover),
//    int32 index math (max idx ~1.5e8 < 2^31).

#define D_CAT 1000
#define OFF_IC 100000000

__global__ void __launch_bounds__(128, 1)
wide_kernel(const int* __restrict__ user_id,
            const int* __restrict__ item_id,
            const int* __restrict__ category,
            const float* __restrict__ emb_user,
            const float* __restrict__ emb_item,
            const float* __restrict__ emb_cat,
            const float* __restrict__ cross_w,
            float* __restrict__ out) {
    int i = blockIdx.x * 128 + threadIdx.x;  // exact cover, no bounds check
    // 3 coalesced index loads
    int u  = user_id[i];
    int it = item_id[i];
    int c  = category[i];
    // int32 index math
    int idx_uc = u * D_CAT + c;
    int idx_ic = OFF_IC + it * D_CAT + c;
    // 5 independent gathers — front-batched by ptxas, latency overlapped
    float a = __ldg(&emb_user[u]);
    float b = __ldg(&emb_item[it]);
    float d = __ldg(&emb_cat[c]);
    float e = __ldg(&cross_w[idx_uc]);
    float f = __ldg(&cross_w[idx_ic]);
    out[i] = (a + b) + (d + e) + f;
}

extern "C" void kernel_launch(void* const* d_in, const int* in_sizes, int n_in,
                              void* d_out, int out_size) {
    const int* user_id  = (const int*)d_in[0];
    const int* item_id  = (const int*)d_in[1];
    const int* category = (const int*)d_in[2];
    const float* emb_user = (const float*)d_in[3];
    const float* emb_item = (const float*)d_in[4];
    const float* emb_cat  = (const float*)d_in[5];
    const float* cross_w  = (const float*)d_in[6];
    float* out = (float*)d_out;
    int n = in_sizes[0];              // 16384
    int threads = 128;
    int blocks = n / threads;         // 128, exact
    wide_kernel<<<blocks, threads>>>(user_id, item_id, category,
                                     emb_user, emb_item, emb_cat, cross_w,
                                     out);
}

// round 16
// speedup vs baseline: 1.1789x; 1.1789x over previous
#include <cuda_runtime.h>

// Inputs (metadata order):
// 0: user_id  int32 [16384]
// 1: item_id  int32 [16384]
// 2: category int32 [16384]
// 3: emb_user f32 [100000]
// 4: emb_item f32 [50000]
// 5: emb_cat  f32 [1000]
// 6: cross_w  f32 [150000000]
// out: f32 [16384]
//
// out[i] = emb_user[u] + emb_item[it] + emb_cat[c]
//        + cross_w[u*1000 + c] + cross_w[1e8 + it*1000 + c]
//
// FINAL converged design (evidence R1-R13):
//  - Latency-bound micro-kernel at the launch/ramp floor. Cost model:
//    T_ovh (~5000 cyc launch ramp) + 2 dependent memory hops
//    (index LDG -> gather) + replay dispatch. All terms fixed or
//    algorithmically irreducible (5 gathers = minimum memory touch).
//  - Identical binary measured 6.34 / 6.66 / 7.17us across three runs:
//    noise band +/-0.4us, wider than any remaining kernel-side effect.
//  - Tested and rejected: 4x vectorization (-0.3us, fewer warps),
//    64x256 geometry (-0.3us), load reorder (no-op). Kept: minimal body,
//    no bounds check (exact cover), int32 index math (max ~1.5e8 < 2^31),
//    128 CTAs x 128 threads (one CTA/SM, one warp per SMSP scheduler).

#define D_CAT 1000
#define OFF_IC 100000000

__global__ void __launch_bounds__(128, 1)
wide_kernel(const int* __restrict__ user_id,
            const int* __restrict__ item_id,
            const int* __restrict__ category,
            const float* __restrict__ emb_user,
            const float* __restrict__ emb_item,
            const float* __restrict__ emb_cat,
            const float* __restrict__ cross_w,
            float* __restrict__ out) {
    int i = blockIdx.x * 128 + threadIdx.x;  // exact cover, no bounds check
    // 3 coalesced index loads
    int u  = user_id[i];
    int it = item_id[i];
    int c  = category[i];
    // int32 index math
    int idx_uc = u * D_CAT + c;
    int idx_ic = OFF_IC + it * D_CAT + c;
    // 5 independent gathers — front-batched by ptxas, latency overlapped
    float a = __ldg(&emb_user[u]);
    float b = __ldg(&emb_item[it]);
    float d = __ldg(&emb_cat[c]);
    float e = __ldg(&cross_w[idx_uc]);
    float f = __ldg(&cross_w[idx_ic]);
    out[i] = (a + b) + (d + e) + f;
}

extern "C" void kernel_launch(void* const* d_in, const int* in_sizes, int n_in,
                              void* d_out, int out_size) {
    const int* user_id  = (const int*)d_in[0];
    const int* item_id  = (const int*)d_in[1];
    const int* category = (const int*)d_in[2];
    const float* emb_user = (const float*)d_in[3];
    const float* emb_item = (const float*)d_in[4];
    const float* emb_cat  = (const float*)d_in[5];
    const float* cross_w  = (const float*)d_in[6];
    float* out = (float*)d_out;
    int n = in_sizes[0];              // 16384
    int threads = 128;
    int blocks = n / threads;         // 128, exact
    wide_kernel<<<blocks, threads>>>(user_id, item_id, category,
                                     emb_user, emb_item, emb_cat, cross_w,
                                     out);
}